// round 14
// baseline (speedup 1.0000x reference)
#include <cuda_runtime.h>
#include <cuda_bf16.h>
#include <cstdint>
#include <cstddef>

#define T_TOK 16384
#define H_DIM 2048
#define N_EXP 64
#define TOPK  8

// ---------------- scratch (no allocations allowed) ----------------
__device__ float g_topw[T_TOK * TOPK];
__device__ int   g_topidx[T_TOK * TOPK];
__device__ float g_sumw[T_TOK];

// ---------------- helpers ----------------
__device__ __forceinline__ void ldsm4(uint32_t& r0, uint32_t& r1, uint32_t& r2, uint32_t& r3,
                                      uint32_t addr) {
    asm volatile("ldmatrix.sync.aligned.m8n8.x4.shared.b16 {%0,%1,%2,%3}, [%4];"
                 : "=r"(r0), "=r"(r1), "=r"(r2), "=r"(r3) : "r"(addr));
}
__device__ __forceinline__ void mma_bf16(float* d, const uint32_t* a, uint32_t b0, uint32_t b1) {
    asm volatile("mma.sync.aligned.m16n8k16.row.col.f32.bf16.bf16.f32 "
                 "{%0,%1,%2,%3},{%4,%5,%6,%7},{%8,%9},{%0,%1,%2,%3};"
                 : "+f"(d[0]), "+f"(d[1]), "+f"(d[2]), "+f"(d[3])
                 : "r"(a[0]), "r"(a[1]), "r"(a[2]), "r"(a[3]), "r"(b0), "r"(b1));
}
__device__ __forceinline__ void hfma2(uint32_t& d, uint32_t a, uint32_t b) {
    asm volatile("fma.rn.bf16x2 %0, %1, %2, %0;" : "+r"(d) : "r"(a), "r"(b));
}

// ================= Kernel A: HMMA router, TOKB=64, 2 CTAs/SM =================
static constexpr int TOKB = 64;
static constexpr int KC   = 64;
static constexpr int NCH  = H_DIM / KC;   // 32

static constexpr int OFF_A  = 0;          // 2 x (Ahi 8192 + Alo 8192) = 32768
static constexpr int OFF_W  = 32768;      // 2 x (Whi 8192 + Wlo 8192) = 32768
static constexpr int OFF_RB = 69632;      // after slog overlay (4*64*68*4 = 69632)
static constexpr int SMEM_R = 69888;

__global__ __launch_bounds__(256, 2)
void router_mma_kernel(const float* __restrict__ X,
                       const float* __restrict__ RW,
                       const float* __restrict__ RB)
{
    extern __shared__ __align__(16) char dsm[];
    const uint32_t sb = (uint32_t)__cvta_generic_to_shared(dsm);
    const int tid  = threadIdx.x;
    const int lane = tid & 31;
    const int wid  = tid >> 5;
    const int tb   = blockIdx.x * TOKB;
    const int kg   = wid & 3;    // k16 step within 64-k chunk
    const int mp   = wid >> 2;   // token half: [mp*32, mp*32+32)

    if (tid < N_EXP) ((float*)(dsm + OFF_RB))[tid] = RB[tid];

    float4 xr[4];   // X chunk: 64 rows x 16 float4 / 256 thr = 4
    float4 wr[4];   // W chunk: 64 rows x 16 float4 / 256 thr = 4

    auto ldgX = [&](int c) {
        const float* src = X + (size_t)tb * H_DIM + c * KC;
        #pragma unroll
        for (int r = 0; r < 4; r++) {
            int idx = tid + r * 256;
            int row = idx >> 4, c16 = idx & 15;
            xr[r] = *(const float4*)(src + (size_t)row * H_DIM + c16 * 4);
        }
    };
    auto ldgW = [&](int c) {
        const float* src = RW + c * KC;
        #pragma unroll
        for (int r = 0; r < 4; r++) {
            int idx = tid + r * 256;
            int row = idx >> 4, c16 = idx & 15;
            wr[r] = *(const float4*)(src + (size_t)row * H_DIM + c16 * 4);
        }
    };

    auto cvt4 = [&](float4 f, uint32_t& h01, uint32_t& h23, uint32_t& l01, uint32_t& l23) {
        asm("cvt.rn.bf16x2.f32 %0, %1, %2;" : "=r"(h01) : "f"(f.y), "f"(f.x));
        asm("cvt.rn.bf16x2.f32 %0, %1, %2;" : "=r"(h23) : "f"(f.w), "f"(f.z));
        float e0 = f.x - __uint_as_float(h01 << 16);
        float e1 = f.y - __uint_as_float(h01 & 0xffff0000u);
        float e2 = f.z - __uint_as_float(h23 << 16);
        float e3 = f.w - __uint_as_float(h23 & 0xffff0000u);
        asm("cvt.rn.bf16x2.f32 %0, %1, %2;" : "=r"(l01) : "f"(e1), "f"(e0));
        asm("cvt.rn.bf16x2.f32 %0, %1, %2;" : "=r"(l23) : "f"(e3), "f"(e2));
    };

    auto convertX = [&](int b) {
        uint32_t ab = sb + OFF_A + (uint32_t)(b * 16384);
        #pragma unroll
        for (int r = 0; r < 4; r++) {
            int idx = tid + r * 256;
            int row = idx >> 4, c16 = idx & 15;
            int rx = row & 7;
            uint32_t h01, h23, l01, l23;
            cvt4(xr[r], h01, h23, l01, l23);
            uint32_t off = (uint32_t)(row * 128 + (((c16 >> 1) ^ rx) << 4) + (c16 & 1) * 8);
            asm volatile("st.shared.v2.b32 [%0], {%1,%2};" :: "r"(ab + off), "r"(h01), "r"(h23));
            asm volatile("st.shared.v2.b32 [%0], {%1,%2};" :: "r"(ab + 8192 + off), "r"(l01), "r"(l23));
        }
    };
    auto convertW = [&](int b) {
        uint32_t wb_ = sb + OFF_W + (uint32_t)(b * 16384);
        #pragma unroll
        for (int r = 0; r < 4; r++) {
            int idx = tid + r * 256;
            int row = idx >> 4, c16 = idx & 15;
            int rx = row & 7;
            uint32_t h01, h23, l01, l23;
            cvt4(wr[r], h01, h23, l01, l23);
            uint32_t off = (uint32_t)(row * 128 + (((c16 >> 1) ^ rx) << 4) + (c16 & 1) * 8);
            asm volatile("st.shared.v2.b32 [%0], {%1,%2};" :: "r"(wb_ + off), "r"(h01), "r"(h23));
            asm volatile("st.shared.v2.b32 [%0], {%1,%2};" :: "r"(wb_ + 8192 + off), "r"(l01), "r"(l23));
        }
    };

    float acc[2][8][4];
    #pragma unroll
    for (int m = 0; m < 2; m++)
        #pragma unroll
        for (int n = 0; n < 8; n++)
            #pragma unroll
            for (int j = 0; j < 4; j++) acc[m][n][j] = 0.f;

    const uint32_t a_roff = (uint32_t)((mp * 32 + (lane & 15)) * 128);
    const uint32_t axor = (uint32_t)((lane & 7) << 4);
    const uint32_t ak16 = (uint32_t)((lane >> 4) << 4);
    const int bq = lane >> 3;
    const uint32_t bn = (uint32_t)(((bq >> 1) << 3) + (lane & 7));
    const uint32_t bkb = (uint32_t)((bq & 1) * 16);
    const uint32_t bxor = (uint32_t)((lane & 7) << 4);
    const uint32_t koff = (uint32_t)(kg * 32);

    ldgX(0); ldgW(0);
    convertX(0); convertW(0);
    ldgX(1); ldgW(1);
    __syncthreads();

    for (int c = 0; c < NCH; c++) {
        if (c + 1 < NCH) { convertX((c + 1) & 1); convertW((c + 1) & 1); }
        if (c + 2 < NCH) { ldgX(c + 2); ldgW(c + 2); }   // LDG before MMA burst

        const uint32_t wbase = sb + OFF_W + (uint32_t)((c & 1) * 16384);
        const uint32_t abuf  = sb + OFF_A + (uint32_t)((c & 1) * 16384);
        uint32_t bh[16], bl[16];
        #pragma unroll
        for (int g = 0; g < 4; g++) {
            uint32_t ba = wbase + (g * 16 + bn) * 128 + ((koff + bkb) ^ bxor);
            ldsm4(bh[g*4], bh[g*4+1], bh[g*4+2], bh[g*4+3], ba);
            ldsm4(bl[g*4], bl[g*4+1], bl[g*4+2], bl[g*4+3], ba + 8192);
        }
        #pragma unroll
        for (int mt = 0; mt < 2; mt++) {
            uint32_t aa = abuf + a_roff + (uint32_t)(mt * 2048) + ((koff + ak16) ^ axor);
            uint32_t ah[4], al[4];
            ldsm4(ah[0], ah[1], ah[2], ah[3], aa);
            ldsm4(al[0], al[1], al[2], al[3], aa + 8192);
            #pragma unroll
            for (int nt = 0; nt < 8; nt++) {
                const int bi = (nt >> 1) * 4 + (nt & 1) * 2;
                mma_bf16(acc[mt][nt], ah, bh[bi], bh[bi+1]);
                mma_bf16(acc[mt][nt], ah, bl[bi], bl[bi+1]);
                mma_bf16(acc[mt][nt], al, bh[bi], bh[bi+1]);
            }
        }

        __syncthreads();
    }

    // ---- epilogue: dump split-K partials, reduce, softmax + top-8 ----
    float* slog = (float*)dsm;                 // [4][64][68] = 69632 B overlay
    #pragma unroll
    for (int mt = 0; mt < 2; mt++)
        #pragma unroll
        for (int nt = 0; nt < 8; nt++)
            #pragma unroll
            for (int j = 0; j < 4; j++) {
                int trow = mp * 32 + mt * 16 + (lane >> 2) + (j >> 1) * 8;
                int e = nt * 8 + (lane & 3) * 2 + (j & 1);
                slog[(kg * 64 + trow) * 68 + e] = acc[mt][nt][j];
            }
    __syncthreads();

    if (tid < TOKB) {
        const float* rb = (const float*)(dsm + OFF_RB);
        const int t = tb + tid;
        float l[N_EXP];
        #pragma unroll
        for (int e = 0; e < N_EXP; e++)
            l[e] = (slog[tid * 68 + e] + slog[(64 + tid) * 68 + e]) +
                   (slog[(128 + tid) * 68 + e] + slog[(192 + tid) * 68 + e]) + rb[e];
        float mx = -1e30f;
        #pragma unroll
        for (int e = 0; e < N_EXP; e++) mx = fmaxf(mx, l[e]);
        float sum = 0.f;
        #pragma unroll
        for (int e = 0; e < N_EXP; e++) { float p = __expf(l[e] - mx); l[e] = p; sum += p; }
        const float inv = 1.0f / sum;
        unsigned long long mask = 0ull;
        float sw = 0.f;
        #pragma unroll
        for (int k = 0; k < TOPK; k++) {
            float best = -1.f; int bi = 0;
            #pragma unroll
            for (int e = 0; e < N_EXP; e++) {
                bool ok = !((mask >> e) & 1ull) && (l[e] > best);
                if (ok) { best = l[e]; bi = e; }
            }
            mask |= 1ull << bi;
            float w = best * inv;
            g_topw[t * TOPK + k]   = w;
            g_topidx[t * TOPK + k] = bi;
            sw += w;
        }
        g_sumw[t] = sw;
    }
}

// ================= Kernel B: combine (packed bf16x2 HFMA2, TBB=256) — R13 =================
static constexpr int TBB = 256;
static constexpr int HCB = 128;

__global__ __launch_bounds__(256)
void combine_kernel(const float* __restrict__ X,
                    const float* __restrict__ EB,
                    float* __restrict__ OUT)
{
    __shared__ __align__(16) uint32_t bs[N_EXP * 64];   // bf16x2 bias slice, 16 KB
    __shared__ __align__(16) uint4 s_meta[TBB * 3];

    const int tid = threadIdx.x;
    const int hb  = blockIdx.x * HCB;
    const int tb0 = blockIdx.y * TBB;

    #pragma unroll
    for (int r = 0; r < 8; r++) {
        int idx = tid + r * 256;
        int e = idx >> 5, c = idx & 31;
        float4 f = *(const float4*)&EB[(size_t)e * H_DIM + hb + c * 4];
        uint32_t p0, p1;
        asm("cvt.rn.bf16x2.f32 %0, %1, %2;" : "=r"(p0) : "f"(f.y), "f"(f.x));
        asm("cvt.rn.bf16x2.f32 %0, %1, %2;" : "=r"(p1) : "f"(f.w), "f"(f.z));
        *(uint2*)&bs[e * 64 + c * 2] = make_uint2(p0, p1);
    }
    {
        const int t = tb0 + tid;
        float4 w0 = *(const float4*)&g_topw[t * TOPK];
        float4 w1 = *(const float4*)&g_topw[t * TOPK + 4];
        int4 i0 = *(const int4*)&g_topidx[t * TOPK];
        int4 i1 = *(const int4*)&g_topidx[t * TOPK + 4];
        uint32_t wk2[8];
        const float wf[8] = {w0.x, w0.y, w0.z, w0.w, w1.x, w1.y, w1.z, w1.w};
        #pragma unroll
        for (int k = 0; k < 8; k++)
            asm("cvt.rn.bf16x2.f32 %0, %1, %2;" : "=r"(wk2[k]) : "f"(wf[k]), "f"(wf[k]));
        uint32_t p03 = (uint32_t)i0.x | ((uint32_t)i0.y << 8) |
                       ((uint32_t)i0.z << 16) | ((uint32_t)i0.w << 24);
        uint32_t p47 = (uint32_t)i1.x | ((uint32_t)i1.y << 8) |
                       ((uint32_t)i1.z << 16) | ((uint32_t)i1.w << 24);
        float sw = wf[0] + wf[1] + wf[2] + wf[3] + wf[4] + wf[5] + wf[6] + wf[7];
        s_meta[tid * 3 + 0] = make_uint4(wk2[0], wk2[1], wk2[2], wk2[3]);
        s_meta[tid * 3 + 1] = make_uint4(wk2[4], wk2[5], wk2[6], wk2[7]);
        s_meta[tid * 3 + 2] = make_uint4(__float_as_uint(sw), p03, p47, 0u);
    }
    __syncthreads();

    const int tl = tid >> 5;
    const int c  = tid & 31;

    float4 xv = __ldcs((const float4*)&X[(size_t)(tb0 + tl) * H_DIM + hb + c * 4]);
    #pragma unroll 4
    for (int it = 0; it < TBB / 8; it++) {
        const int tt = tl + it * 8;
        float4 xn = xv;
        if (it + 1 < TBB / 8)
            xn = __ldcs((const float4*)&X[(size_t)(tb0 + tt + 8) * H_DIM + hb + c * 4]);

        const uint4 mw0 = s_meta[tt * 3 + 0];
        const uint4 mw1 = s_meta[tt * 3 + 1];
        const uint4 m2  = s_meta[tt * 3 + 2];
        const float sw = __uint_as_float(m2.x);
        const uint32_t i03 = m2.y, i47 = m2.z;
        const uint32_t wk2[8] = {mw0.x, mw0.y, mw0.z, mw0.w, mw1.x, mw1.y, mw1.z, mw1.w};

        uint32_t ap0 = 0u, ap1 = 0u;
        #pragma unroll
        for (int k = 0; k < TOPK; k++) {
            const uint32_t ek = ((k < 4 ? (i03 >> (k * 8)) : (i47 >> ((k - 4) * 8))) & 0xffu);
            const uint2 b2 = *(const uint2*)&bs[ek * 64 + c * 2];
            hfma2(ap0, wk2[k], b2.x);
            hfma2(ap1, wk2[k], b2.y);
        }
        float4 a;
        a.x = fmaf(xv.x, sw, __uint_as_float(ap0 << 16));
        a.y = fmaf(xv.y, sw, __uint_as_float(ap0 & 0xffff0000u));
        a.z = fmaf(xv.z, sw, __uint_as_float(ap1 << 16));
        a.w = fmaf(xv.w, sw, __uint_as_float(ap1 & 0xffff0000u));
        __stcs((float4*)&OUT[(size_t)(tb0 + tt) * H_DIM + hb + c * 4], a);
        xv = xn;
    }
}

// ================= launch =================
extern "C" void kernel_launch(void* const* d_in, const int* in_sizes, int n_in,
                              void* d_out, int out_size) {
    const float* X  = (const float*)d_in[0];   // hidden_states [4,4096,2048]
    const float* RW = (const float*)d_in[1];   // router_weight [64,2048]
    const float* RB = (const float*)d_in[2];   // router_bias   [64]
    const float* EB = (const float*)d_in[3];   // expert_bias   [64,2048]
    float* OUT = (float*)d_out;

    cudaFuncSetAttribute(router_mma_kernel,
                         cudaFuncAttributeMaxDynamicSharedMemorySize, SMEM_R);

    router_mma_kernel<<<T_TOK / TOKB, 256, SMEM_R>>>(X, RW, RB);
    dim3 gb(H_DIM / HCB, T_TOK / TBB);
    combine_kernel<<<gb, 256>>>(X, EB, OUT);
}

// round 15
// speedup vs baseline: 1.3186x; 1.3186x over previous
#include <cuda_runtime.h>
#include <cuda_bf16.h>
#include <cstdint>
#include <cstddef>

#define T_TOK 16384
#define H_DIM 2048
#define N_EXP 64
#define TOPK  8

// ---------------- scratch (no allocations allowed) ----------------
__device__ float g_topw[T_TOK * TOPK];
__device__ int   g_topidx[T_TOK * TOPK];
__device__ float g_sumw[T_TOK];

// ---------------- helpers ----------------
__device__ __forceinline__ void ldsm4(uint32_t& r0, uint32_t& r1, uint32_t& r2, uint32_t& r3,
                                      uint32_t addr) {
    asm volatile("ldmatrix.sync.aligned.m8n8.x4.shared.b16 {%0,%1,%2,%3}, [%4];"
                 : "=r"(r0), "=r"(r1), "=r"(r2), "=r"(r3) : "r"(addr));
}
__device__ __forceinline__ void mma_bf16(float* d, const uint32_t* a, uint32_t b0, uint32_t b1) {
    asm volatile("mma.sync.aligned.m16n8k16.row.col.f32.bf16.bf16.f32 "
                 "{%0,%1,%2,%3},{%4,%5,%6,%7},{%8,%9},{%0,%1,%2,%3};"
                 : "+f"(d[0]), "+f"(d[1]), "+f"(d[2]), "+f"(d[3])
                 : "r"(a[0]), "r"(a[1]), "r"(a[2]), "r"(a[3]), "r"(b0), "r"(b1));
}
__device__ __forceinline__ void hfma2(uint32_t& d, uint32_t a, uint32_t b) {
    asm volatile("fma.rn.bf16x2 %0, %1, %2, %0;" : "+r"(d) : "r"(a), "r"(b));
}

// ================= Kernel A: HMMA router (bf16 hi/lo x3), all-LDG — R12/R13 =================
static constexpr int TOKB = 128;
static constexpr int KC   = 64;
static constexpr int NCH  = H_DIM / KC;   // 32

static constexpr int OFF_A  = 0;          // 2 x (Ahi 16384 + Alo 16384) = 65536
static constexpr int OFF_W  = 65536;      // 2 x (Whi 8192  + Wlo 8192)  = 32768
static constexpr int OFF_RB = 139264;     // after slog overlay (4*128*68*4 = 139264)
static constexpr int SMEM_R = 139520;

__global__ __launch_bounds__(256, 1)
void router_mma_kernel(const float* __restrict__ X,
                       const float* __restrict__ RW,
                       const float* __restrict__ RB)
{
    extern __shared__ __align__(16) char dsm[];
    const uint32_t sb = (uint32_t)__cvta_generic_to_shared(dsm);
    const int tid  = threadIdx.x;
    const int lane = tid & 31;
    const int wid  = tid >> 5;
    const int tb   = blockIdx.x * TOKB;
    const int kg   = wid & 3;
    const int mp   = wid >> 2;

    if (tid < N_EXP) ((float*)(dsm + OFF_RB))[tid] = RB[tid];

    float4 xr[8];
    float4 wr[4];

    auto ldgX = [&](int c) {
        const float* src = X + (size_t)tb * H_DIM + c * KC;
        #pragma unroll
        for (int r = 0; r < 8; r++) {
            int idx = tid + r * 256;
            int row = idx >> 4, c16 = idx & 15;
            xr[r] = *(const float4*)(src + (size_t)row * H_DIM + c16 * 4);
        }
    };
    auto ldgW = [&](int c) {
        const float* src = RW + c * KC;
        #pragma unroll
        for (int r = 0; r < 4; r++) {
            int idx = tid + r * 256;
            int row = idx >> 4, c16 = idx & 15;
            wr[r] = *(const float4*)(src + (size_t)row * H_DIM + c16 * 4);
        }
    };

    auto cvt4 = [&](float4 f, uint32_t& h01, uint32_t& h23, uint32_t& l01, uint32_t& l23) {
        asm("cvt.rn.bf16x2.f32 %0, %1, %2;" : "=r"(h01) : "f"(f.y), "f"(f.x));
        asm("cvt.rn.bf16x2.f32 %0, %1, %2;" : "=r"(h23) : "f"(f.w), "f"(f.z));
        float e0 = f.x - __uint_as_float(h01 << 16);
        float e1 = f.y - __uint_as_float(h01 & 0xffff0000u);
        float e2 = f.z - __uint_as_float(h23 << 16);
        float e3 = f.w - __uint_as_float(h23 & 0xffff0000u);
        asm("cvt.rn.bf16x2.f32 %0, %1, %2;" : "=r"(l01) : "f"(e1), "f"(e0));
        asm("cvt.rn.bf16x2.f32 %0, %1, %2;" : "=r"(l23) : "f"(e3), "f"(e2));
    };

    auto convertX = [&](int b) {
        uint32_t ab = sb + OFF_A + (uint32_t)(b * 32768);
        #pragma unroll
        for (int r = 0; r < 8; r++) {
            int idx = tid + r * 256;
            int row = idx >> 4, c16 = idx & 15;
            int rx = row & 7;
            uint32_t h01, h23, l01, l23;
            cvt4(xr[r], h01, h23, l01, l23);
            uint32_t off = (uint32_t)(row * 128 + (((c16 >> 1) ^ rx) << 4) + (c16 & 1) * 8);
            asm volatile("st.shared.v2.b32 [%0], {%1,%2};" :: "r"(ab + off), "r"(h01), "r"(h23));
            asm volatile("st.shared.v2.b32 [%0], {%1,%2};" :: "r"(ab + 16384 + off), "r"(l01), "r"(l23));
        }
    };
    auto convertW = [&](int b) {
        uint32_t wb_ = sb + OFF_W + (uint32_t)(b * 16384);
        #pragma unroll
        for (int r = 0; r < 4; r++) {
            int idx = tid + r * 256;
            int row = idx >> 4, c16 = idx & 15;
            int rx = row & 7;
            uint32_t h01, h23, l01, l23;
            cvt4(wr[r], h01, h23, l01, l23);
            uint32_t off = (uint32_t)(row * 128 + (((c16 >> 1) ^ rx) << 4) + (c16 & 1) * 8);
            asm volatile("st.shared.v2.b32 [%0], {%1,%2};" :: "r"(wb_ + off), "r"(h01), "r"(h23));
            asm volatile("st.shared.v2.b32 [%0], {%1,%2};" :: "r"(wb_ + 8192 + off), "r"(l01), "r"(l23));
        }
    };

    float acc[4][8][4];
    #pragma unroll
    for (int m = 0; m < 4; m++)
        #pragma unroll
        for (int n = 0; n < 8; n++)
            #pragma unroll
            for (int j = 0; j < 4; j++) acc[m][n][j] = 0.f;

    const uint32_t a_roff = (uint32_t)((mp * 64 + (lane & 15)) * 128);
    const uint32_t axor = (uint32_t)((lane & 7) << 4);
    const uint32_t ak16 = (uint32_t)((lane >> 4) << 4);
    const int bq = lane >> 3;
    const uint32_t bn = (uint32_t)(((bq >> 1) << 3) + (lane & 7));
    const uint32_t bkb = (uint32_t)((bq & 1) * 16);
    const uint32_t bxor = (uint32_t)((lane & 7) << 4);
    const uint32_t koff = (uint32_t)(kg * 32);

    ldgX(0); ldgW(0);
    convertX(0); convertW(0);
    ldgX(1); ldgW(1);
    __syncthreads();

    for (int c = 0; c < NCH; c++) {
        if (c + 1 < NCH) { convertX((c + 1) & 1); convertW((c + 1) & 1); }
        if (c + 2 < NCH) { ldgX(c + 2); ldgW(c + 2); }   // LDG before MMA burst

        const uint32_t wbase = sb + OFF_W + (uint32_t)((c & 1) * 16384);
        const uint32_t abuf  = sb + OFF_A + (uint32_t)((c & 1) * 32768);
        uint32_t bh[16], bl[16];
        #pragma unroll
        for (int g = 0; g < 4; g++) {
            uint32_t ba = wbase + (g * 16 + bn) * 128 + ((koff + bkb) ^ bxor);
            ldsm4(bh[g*4], bh[g*4+1], bh[g*4+2], bh[g*4+3], ba);
            ldsm4(bl[g*4], bl[g*4+1], bl[g*4+2], bl[g*4+3], ba + 8192);
        }
        #pragma unroll
        for (int mt = 0; mt < 4; mt++) {
            uint32_t aa = abuf + a_roff + (uint32_t)(mt * 2048) + ((koff + ak16) ^ axor);
            uint32_t ah[4], al[4];
            ldsm4(ah[0], ah[1], ah[2], ah[3], aa);
            ldsm4(al[0], al[1], al[2], al[3], aa + 16384);
            #pragma unroll
            for (int nt = 0; nt < 8; nt++) {
                const int bi = (nt >> 1) * 4 + (nt & 1) * 2;
                mma_bf16(acc[mt][nt], ah, bh[bi], bh[bi+1]);
                mma_bf16(acc[mt][nt], ah, bl[bi], bl[bi+1]);
                mma_bf16(acc[mt][nt], al, bh[bi], bh[bi+1]);
            }
        }

        __syncthreads();
    }

    float* slog = (float*)dsm;                 // [4][128][68]
    #pragma unroll
    for (int mt = 0; mt < 4; mt++)
        #pragma unroll
        for (int nt = 0; nt < 8; nt++)
            #pragma unroll
            for (int j = 0; j < 4; j++) {
                int trow = mp * 64 + mt * 16 + (lane >> 2) + (j >> 1) * 8;
                int e = nt * 8 + (lane & 3) * 2 + (j & 1);
                slog[(kg * 128 + trow) * 68 + e] = acc[mt][nt][j];
            }
    __syncthreads();

    if (tid < TOKB) {
        const float* rb = (const float*)(dsm + OFF_RB);
        const int t = tb + tid;
        float l[N_EXP];
        #pragma unroll
        for (int e = 0; e < N_EXP; e++)
            l[e] = (slog[tid * 68 + e] + slog[(128 + tid) * 68 + e]) +
                   (slog[(256 + tid) * 68 + e] + slog[(384 + tid) * 68 + e]) + rb[e];
        float mx = -1e30f;
        #pragma unroll
        for (int e = 0; e < N_EXP; e++) mx = fmaxf(mx, l[e]);
        float sum = 0.f;
        #pragma unroll
        for (int e = 0; e < N_EXP; e++) { float p = __expf(l[e] - mx); l[e] = p; sum += p; }
        const float inv = 1.0f / sum;
        unsigned long long mask = 0ull;
        float sw = 0.f;
        #pragma unroll
        for (int k = 0; k < TOPK; k++) {
            float best = -1.f; int bi = 0;
            #pragma unroll
            for (int e = 0; e < N_EXP; e++) {
                bool ok = !((mask >> e) & 1ull) && (l[e] > best);
                if (ok) { best = l[e]; bi = e; }
            }
            mask |= 1ull << bi;
            float w = best * inv;
            g_topw[t * TOPK + k]   = w;
            g_topidx[t * TOPK + k] = bi;
            sw += w;
        }
        g_sumw[t] = sw;
    }
}

// ================= Kernel B: combine (HFMA2 + MLP-4 batched X loads) =================
static constexpr int TBB = 256;
static constexpr int HCB = 128;

__global__ __launch_bounds__(256)
void combine_kernel(const float* __restrict__ X,
                    const float* __restrict__ EB,
                    float* __restrict__ OUT)
{
    __shared__ __align__(16) uint32_t bs[N_EXP * 64];   // bf16x2 bias slice, 16 KB
    __shared__ __align__(16) uint4 s_meta[TBB * 3];

    const int tid = threadIdx.x;
    const int hb  = blockIdx.x * HCB;
    const int tb0 = blockIdx.y * TBB;

    #pragma unroll
    for (int r = 0; r < 8; r++) {
        int idx = tid + r * 256;
        int e = idx >> 5, c = idx & 31;
        float4 f = *(const float4*)&EB[(size_t)e * H_DIM + hb + c * 4];
        uint32_t p0, p1;
        asm("cvt.rn.bf16x2.f32 %0, %1, %2;" : "=r"(p0) : "f"(f.y), "f"(f.x));
        asm("cvt.rn.bf16x2.f32 %0, %1, %2;" : "=r"(p1) : "f"(f.w), "f"(f.z));
        *(uint2*)&bs[e * 64 + c * 2] = make_uint2(p0, p1);
    }
    {
        const int t = tb0 + tid;
        float4 w0 = *(const float4*)&g_topw[t * TOPK];
        float4 w1 = *(const float4*)&g_topw[t * TOPK + 4];
        int4 i0 = *(const int4*)&g_topidx[t * TOPK];
        int4 i1 = *(const int4*)&g_topidx[t * TOPK + 4];
        uint32_t wk2[8];
        const float wf[8] = {w0.x, w0.y, w0.z, w0.w, w1.x, w1.y, w1.z, w1.w};
        #pragma unroll
        for (int k = 0; k < 8; k++)
            asm("cvt.rn.bf16x2.f32 %0, %1, %2;" : "=r"(wk2[k]) : "f"(wf[k]), "f"(wf[k]));
        uint32_t p03 = (uint32_t)i0.x | ((uint32_t)i0.y << 8) |
                       ((uint32_t)i0.z << 16) | ((uint32_t)i0.w << 24);
        uint32_t p47 = (uint32_t)i1.x | ((uint32_t)i1.y << 8) |
                       ((uint32_t)i1.z << 16) | ((uint32_t)i1.w << 24);
        float sw = wf[0] + wf[1] + wf[2] + wf[3] + wf[4] + wf[5] + wf[6] + wf[7];
        s_meta[tid * 3 + 0] = make_uint4(wk2[0], wk2[1], wk2[2], wk2[3]);
        s_meta[tid * 3 + 1] = make_uint4(wk2[4], wk2[5], wk2[6], wk2[7]);
        s_meta[tid * 3 + 2] = make_uint4(__float_as_uint(sw), p03, p47, 0u);
    }
    __syncthreads();

    const int tl = tid >> 5;
    const int c  = tid & 31;

    // 32 token-iterations in 8 groups of 4; all 4 X loads issued back-to-back.
    #pragma unroll
    for (int g = 0; g < TBB / 32; g++) {
        float4 xv[4];
        #pragma unroll
        for (int u = 0; u < 4; u++) {
            const int tt = tl + (g * 4 + u) * 8;
            xv[u] = __ldcs((const float4*)&X[(size_t)(tb0 + tt) * H_DIM + hb + c * 4]);
        }
        #pragma unroll
        for (int u = 0; u < 4; u++) {
            const int tt = tl + (g * 4 + u) * 8;
            const uint4 mw0 = s_meta[tt * 3 + 0];
            const uint4 mw1 = s_meta[tt * 3 + 1];
            const uint4 m2  = s_meta[tt * 3 + 2];
            const float sw = __uint_as_float(m2.x);
            const uint32_t i03 = m2.y, i47 = m2.z;
            const uint32_t wk2[8] = {mw0.x, mw0.y, mw0.z, mw0.w, mw1.x, mw1.y, mw1.z, mw1.w};

            uint32_t ap0 = 0u, ap1 = 0u;
            #pragma unroll
            for (int k = 0; k < TOPK; k++) {
                const uint32_t ek = ((k < 4 ? (i03 >> (k * 8)) : (i47 >> ((k - 4) * 8))) & 0xffu);
                const uint2 b2 = *(const uint2*)&bs[ek * 64 + c * 2];
                hfma2(ap0, wk2[k], b2.x);
                hfma2(ap1, wk2[k], b2.y);
            }
            float4 a;
            a.x = fmaf(xv[u].x, sw, __uint_as_float(ap0 << 16));
            a.y = fmaf(xv[u].y, sw, __uint_as_float(ap0 & 0xffff0000u));
            a.z = fmaf(xv[u].z, sw, __uint_as_float(ap1 << 16));
            a.w = fmaf(xv[u].w, sw, __uint_as_float(ap1 & 0xffff0000u));
            __stcs((float4*)&OUT[(size_t)(tb0 + tt) * H_DIM + hb + c * 4], a);
        }
    }
}

// ================= launch =================
extern "C" void kernel_launch(void* const* d_in, const int* in_sizes, int n_in,
                              void* d_out, int out_size) {
    const float* X  = (const float*)d_in[0];   // hidden_states [4,4096,2048]
    const float* RW = (const float*)d_in[1];   // router_weight [64,2048]
    const float* RB = (const float*)d_in[2];   // router_bias   [64]
    const float* EB = (const float*)d_in[3];   // expert_bias   [64,2048]
    float* OUT = (float*)d_out;

    cudaFuncSetAttribute(router_mma_kernel,
                         cudaFuncAttributeMaxDynamicSharedMemorySize, SMEM_R);

    router_mma_kernel<<<T_TOK / TOKB, 256, SMEM_R>>>(X, RW, RB);
    dim3 gb(H_DIM / HCB, T_TOK / TBB);
    combine_kernel<<<gb, 256>>>(X, EB, OUT);
}